// round 2
// baseline (speedup 1.0000x reference)
#include <cuda_runtime.h>

#define N   8192
#define DIM 128
#define E   262144

// Scratch (device globals -- allocation-free per harness rules)
__device__ float g_inv_nrm[N];
__device__ float g_dis[N];          // deg (init 1.0 for self loop) -> dis
__device__ float g_M[DIM * DIM];    // Y^T x
__device__ float g_dxw[N * DIM];    // (x @ W) * dis[row]
__device__ float g_acc[N * DIM];    // GCN scatter accumulator

// ---------------------------------------------------------------- K1: init
__global__ void k_init() {
    int i = blockIdx.x * blockDim.x + threadIdx.x;
    if (i < (N * DIM) / 4) ((float4*)g_acc)[i] = make_float4(0.f, 0.f, 0.f, 0.f);
    if (i < DIM * DIM) g_M[i] = 0.f;
    if (i < N) g_dis[i] = 1.0f;   // self-loop contributes 1 to deg
}

// ------------------------------------------------------------- K2: inv norms
__global__ void k_norms(const float* __restrict__ x) {
    int w = threadIdx.x >> 5, lane = threadIdx.x & 31;
    int row = blockIdx.x * 8 + w;
    float4 v = ((const float4*)x)[row * 32 + lane];
    float s = v.x * v.x + v.y * v.y + v.z * v.z + v.w * v.w;
    #pragma unroll
    for (int o = 16; o; o >>= 1) s += __shfl_xor_sync(0xffffffffu, s, o);
    if (lane == 0) g_inv_nrm[row] = rsqrtf(s);
}

// ------------------------------------------------- K3: M = Y^T x  (128x128)
// 128 blocks x 256 threads; each block reduces 64 rows, 8x8 register tiles,
// atomic-accumulate into g_M.
__global__ void k_maccum(const float* __restrict__ x) {
    __shared__ float xs[8][DIM];
    __shared__ float invs[8];
    int tid = threadIdx.x;
    int tx = tid & 15, ty = tid >> 4;
    int k0 = ty * 8, d0 = tx * 8;
    float acc[8][8] = {};
    int row_base = blockIdx.x * 64;
    for (int p = 0; p < 8; p++) {
        int r0 = row_base + p * 8;
        {   // stage 8x128 floats (1024) as 256 float4s
            int rr = tid >> 5;      // row within panel
            int cc = tid & 31;      // float4 within row
            float4 v = ((const float4*)x)[(r0 + rr) * 32 + cc];
            ((float4*)&xs[rr][0])[cc] = v;
        }
        if (tid < 8) invs[tid] = g_inv_nrm[r0 + tid];
        __syncthreads();
        #pragma unroll
        for (int r = 0; r < 8; r++) {
            float inv = invs[r];
            float yk[8], xd[8];
            #pragma unroll
            for (int j = 0; j < 8; j++) yk[j] = xs[r][k0 + j] * inv;
            #pragma unroll
            for (int l = 0; l < 8; l++) xd[l] = xs[r][d0 + l];
            #pragma unroll
            for (int j = 0; j < 8; j++)
                #pragma unroll
                for (int l = 0; l < 8; l++)
                    acc[j][l] += yk[j] * xd[l];
        }
        __syncthreads();
    }
    #pragma unroll
    for (int j = 0; j < 8; j++)
        #pragma unroll
        for (int l = 0; l < 8; l++)
            atomicAdd(&g_M[(k0 + j) * DIM + (d0 + l)], acc[j][l]);
}

// ------------------------------------------------------------- K4: degrees
__global__ void k_deg(const int* __restrict__ ei) {
    int i = blockIdx.x * blockDim.x + threadIdx.x;
    if (i < E) atomicAdd(&g_dis[ei[E + i]], 1.0f);
}

// ------------------------------------------------------------ K5: deg^-1/2
__global__ void k_dis() {
    int i = blockIdx.x * blockDim.x + threadIdx.x;
    if (i < N) g_dis[i] = rsqrtf(g_dis[i]);
}

// --------------------------------------- K6: dxw = (x @ W) * dis, warp/row
__global__ void k_dxw(const float* __restrict__ x, const float* __restrict__ W) {
    extern __shared__ float sm6[];
    float* Ws   = sm6;                 // 16384 floats
    float* rows = sm6 + DIM * DIM;     // 8*128 floats
    int tid = threadIdx.x;
    for (int i = tid; i < (DIM * DIM) / 4; i += 256)
        ((float4*)Ws)[i] = ((const float4*)W)[i];
    __syncthreads();
    int w = tid >> 5, lane = tid & 31;
    int row = blockIdx.x * 8 + w;
    float* myrow = rows + w * DIM;
    float4 xv = ((const float4*)x)[row * 32 + lane];
    ((float4*)myrow)[lane] = xv;
    __syncwarp();
    float4 acc = make_float4(0.f, 0.f, 0.f, 0.f);
    #pragma unroll 16
    for (int k = 0; k < DIM; k++) {
        float xk = myrow[k];
        float4 wv = ((float4*)Ws)[k * 32 + lane];
        acc.x += xk * wv.x; acc.y += xk * wv.y;
        acc.z += xk * wv.z; acc.w += xk * wv.w;
    }
    float di = g_dis[row];
    acc.x *= di; acc.y *= di; acc.z *= di; acc.w *= di;
    ((float4*)g_dxw)[row * 32 + lane] = acc;
}

// ------------------------------------------- K7: edge scatter, vector red
__global__ void k_scatter(const int* __restrict__ ei) {
    int w = threadIdx.x >> 5, lane = threadIdx.x & 31;
    int e = blockIdx.x * 8 + w;
    int row = __ldg(&ei[e]);
    int col = __ldg(&ei[E + e]);
    float s = g_dis[col];
    float4 v = ((const float4*)g_dxw)[row * 32 + lane];
    v.x *= s; v.y *= s; v.z *= s; v.w *= s;
    float* dst = g_acc + (size_t)col * DIM + lane * 4;
    asm volatile("red.global.add.v4.f32 [%0], {%1, %2, %3, %4};"
                 :: "l"(dst), "f"(v.x), "f"(v.y), "f"(v.z), "f"(v.w)
                 : "memory");
}

// --------------- K8: out = (acc + dxw*dis + b) * sigmoid(y . M), warp/row
__global__ void k_final(const float* __restrict__ x, const float* __restrict__ b,
                        float* __restrict__ out) {
    extern __shared__ float sm8[];
    float* Ms   = sm8;                         // 16384
    float* rows = sm8 + DIM * DIM;             // 8*128
    float* bs   = rows + 8 * DIM;              // 128
    int tid = threadIdx.x;
    for (int i = tid; i < (DIM * DIM) / 4; i += 256)
        ((float4*)Ms)[i] = ((const float4*)g_M)[i];
    if (tid < 32) ((float4*)bs)[tid] = ((const float4*)b)[tid];
    __syncthreads();
    int w = tid >> 5, lane = tid & 31;
    int row = blockIdx.x * 8 + w;
    float inv = g_inv_nrm[row];
    float* myrow = rows + w * DIM;
    float4 xv = ((const float4*)x)[row * 32 + lane];
    xv.x *= inv; xv.y *= inv; xv.z *= inv; xv.w *= inv;
    ((float4*)myrow)[lane] = xv;
    __syncwarp();
    float4 a = make_float4(0.f, 0.f, 0.f, 0.f);
    #pragma unroll 16
    for (int k = 0; k < DIM; k++) {
        float yk = myrow[k];
        float4 mv = ((float4*)Ms)[k * 32 + lane];
        a.x += yk * mv.x; a.y += yk * mv.y;
        a.z += yk * mv.z; a.w += yk * mv.w;
    }
    a.x = 1.f / (1.f + __expf(-a.x));
    a.y = 1.f / (1.f + __expf(-a.y));
    a.z = 1.f / (1.f + __expf(-a.z));
    a.w = 1.f / (1.f + __expf(-a.w));
    float di = g_dis[row];
    float4 g  = ((const float4*)g_acc)[row * 32 + lane];
    float4 dx = ((const float4*)g_dxw)[row * 32 + lane];
    float4 bb = ((float4*)bs)[lane];
    float4 o;
    o.x = (g.x + dx.x * di + bb.x) * a.x;
    o.y = (g.y + dx.y * di + bb.y) * a.y;
    o.z = (g.z + dx.z * di + bb.z) * a.z;
    o.w = (g.w + dx.w * di + bb.w) * a.w;
    ((float4*)out)[row * 32 + lane] = o;
}

// ---------------------------------------------------------------- launcher
extern "C" void kernel_launch(void* const* d_in, const int* in_sizes, int n_in,
                              void* d_out, int out_size) {
    const float* x  = (const float*)d_in[0];
    const int*   ei = (const int*)d_in[1];
    const float* W  = (const float*)d_in[2];
    const float* b  = (const float*)d_in[3];
    float* out = (float*)d_out;

    const int SMEM6 = (DIM * DIM + 8 * DIM) * 4;        // 69632
    const int SMEM8 = (DIM * DIM + 8 * DIM + DIM) * 4;  // 70144
    cudaFuncSetAttribute(k_dxw,   cudaFuncAttributeMaxDynamicSharedMemorySize, SMEM6);
    cudaFuncSetAttribute(k_final, cudaFuncAttributeMaxDynamicSharedMemorySize, SMEM8);

    k_init<<<1024, 256>>>();
    k_norms<<<N / 8, 256>>>(x);
    k_maccum<<<128, 256>>>(x);
    k_deg<<<E / 256, 256>>>(ei);
    k_dis<<<32, 256>>>();
    k_dxw<<<N / 8, 256, SMEM6>>>(x, W);
    k_scatter<<<E / 8, 256>>>(ei);
    k_final<<<N / 8, 256, SMEM8>>>(x, b, out);
}